// round 1
// baseline (speedup 1.0000x reference)
#include <cuda_runtime.h>

// Fused attention: out = softmax(x1 @ x2^T * SCALE) @ x2
// B=16, L=2048, D=128, fp32. Flash-attention style, one pass over K.
//
// CTA = (batch, 64-row Q tile). 256 threads as 16x16 grid (tx, ty).
// Thread owns S[ty+16i][tx+16j] (4x4) and O[ty+16i][tx+16jj] (4x8).
// Lane mapping chosen so LDS in both GEMM inner loops is bank-conflict-free.

#define BQ 64
#define BK 64
#define DIM 128
#define LSEQ 2048
#define NBATCH 16
#define QPAD 132   // row stride (floats) for Q/K tiles; mult of 4, conflict-free
#define PPAD 68    // row stride for P tile
#define NKT (LSEQ / BK)

__device__ __forceinline__ float dot4(float4 a, float4 b, float acc) {
    acc = fmaf(a.x, b.x, acc);
    acc = fmaf(a.y, b.y, acc);
    acc = fmaf(a.z, b.z, acc);
    acc = fmaf(a.w, b.w, acc);
    return acc;
}

__global__ __launch_bounds__(256, 2)
void attn_fwd_kernel(const float* __restrict__ x1,
                     const float* __restrict__ x2,
                     float* __restrict__ out) {
    extern __shared__ float smem[];
    float* Qs = smem;                  // BQ * QPAD
    float* Ks = Qs + BQ * QPAD;        // BK * QPAD  (doubles as V tile)
    float* Ps = Ks + BK * QPAD;        // BQ * PPAD

    const float SCALE = 0.08838834764831845f;

    const int b  = blockIdx.y;
    const int qt = blockIdx.x;
    const int tid = threadIdx.x;
    const int tx = tid & 15;
    const int ty = tid >> 4;

    const float* qg = x1 + ((size_t)b * LSEQ + (size_t)qt * BQ) * DIM;
    const float* kg = x2 + (size_t)b * LSEQ * DIM;

    // ---- load Q tile (coalesced float4) ----
    #pragma unroll
    for (int e = tid; e < BQ * DIM / 4; e += 256) {
        int r = e >> 5;          // row 0..63
        int c4 = e & 31;         // float4 col 0..31
        float4 v = reinterpret_cast<const float4*>(qg)[r * (DIM / 4) + c4];
        *reinterpret_cast<float4*>(&Qs[r * QPAD + c4 * 4]) = v;
    }

    // ---- accumulators ----
    float o[4][8];
    #pragma unroll
    for (int i = 0; i < 4; i++)
        #pragma unroll
        for (int jj = 0; jj < 8; jj++) o[i][jj] = 0.0f;

    float m_i[4], l_i[4];
    #pragma unroll
    for (int i = 0; i < 4; i++) { m_i[i] = -1e30f; l_i[i] = 0.0f; }

    for (int kt = 0; kt < NKT; kt++) {
        __syncthreads();  // protect Ks/Ps from previous iteration's readers

        // ---- load K/V tile ----
        const float* kp = kg + (size_t)kt * BK * DIM;
        #pragma unroll
        for (int e = tid; e < BK * DIM / 4; e += 256) {
            int r = e >> 5;
            int c4 = e & 31;
            float4 v = reinterpret_cast<const float4*>(kp)[r * (DIM / 4) + c4];
            *reinterpret_cast<float4*>(&Ks[r * QPAD + c4 * 4]) = v;
        }
        __syncthreads();

        // ---- S = Q @ K^T (64x64 tile), register-blocked 4x4 ----
        float s[4][4];
        #pragma unroll
        for (int i = 0; i < 4; i++)
            #pragma unroll
            for (int j = 0; j < 4; j++) s[i][j] = 0.0f;

        #pragma unroll 4
        for (int d4 = 0; d4 < DIM / 4; d4++) {
            float4 qv[4], kv[4];
            #pragma unroll
            for (int i = 0; i < 4; i++)
                qv[i] = *reinterpret_cast<const float4*>(&Qs[(ty + 16 * i) * QPAD + d4 * 4]);
            #pragma unroll
            for (int j = 0; j < 4; j++)
                kv[j] = *reinterpret_cast<const float4*>(&Ks[(tx + 16 * j) * QPAD + d4 * 4]);
            #pragma unroll
            for (int i = 0; i < 4; i++)
                #pragma unroll
                for (int j = 0; j < 4; j++)
                    s[i][j] = dot4(qv[i], kv[j], s[i][j]);
        }

        // ---- online softmax update ----
        #pragma unroll
        for (int i = 0; i < 4; i++) {
            #pragma unroll
            for (int j = 0; j < 4; j++) s[i][j] *= SCALE;

            float mx = fmaxf(fmaxf(s[i][0], s[i][1]), fmaxf(s[i][2], s[i][3]));
            #pragma unroll
            for (int off = 8; off > 0; off >>= 1)
                mx = fmaxf(mx, __shfl_xor_sync(0xffffffffu, mx, off));

            float mn = fmaxf(m_i[i], mx);
            float corr = __expf(m_i[i] - mn);
            m_i[i] = mn;

            float rs = 0.0f;
            #pragma unroll
            for (int j = 0; j < 4; j++) {
                float p = __expf(s[i][j] - mn);
                rs += p;
                Ps[(ty + 16 * i) * PPAD + tx + 16 * j] = p;
            }
            #pragma unroll
            for (int off = 8; off > 0; off >>= 1)
                rs += __shfl_xor_sync(0xffffffffu, rs, off);

            l_i[i] = l_i[i] * corr + rs;
            #pragma unroll
            for (int jj = 0; jj < 8; jj++) o[i][jj] *= corr;
        }
        __syncthreads();  // Ps visible to all; Ks still holds V

        // ---- O += P @ V (64x64 @ 64x128), register-blocked 4x8 ----
        #pragma unroll 2
        for (int c = 0; c < BK; c++) {
            float pl[4], vl[8];
            #pragma unroll
            for (int i = 0; i < 4; i++)
                pl[i] = Ps[(ty + 16 * i) * PPAD + c];
            #pragma unroll
            for (int jj = 0; jj < 8; jj++)
                vl[jj] = Ks[c * QPAD + tx + 16 * jj];
            #pragma unroll
            for (int i = 0; i < 4; i++)
                #pragma unroll
                for (int jj = 0; jj < 8; jj++)
                    o[i][jj] = fmaf(pl[i], vl[jj], o[i][jj]);
        }
    }

    // ---- normalize and write out (coalesced across tx) ----
    float* og = out + ((size_t)b * LSEQ + (size_t)qt * BQ) * DIM;
    #pragma unroll
    for (int i = 0; i < 4; i++) {
        float inv = 1.0f / l_i[i];
        #pragma unroll
        for (int jj = 0; jj < 8; jj++)
            og[(ty + 16 * i) * DIM + tx + 16 * jj] = o[i][jj] * inv;
    }
}

extern "C" void kernel_launch(void* const* d_in, const int* in_sizes, int n_in,
                              void* d_out, int out_size) {
    const float* x1 = (const float*)d_in[0];
    const float* x2 = (const float*)d_in[1];
    float* out = (float*)d_out;

    int smem_bytes = (BQ * QPAD + BK * QPAD + BQ * PPAD) * (int)sizeof(float); // 84992
    cudaFuncSetAttribute(attn_fwd_kernel,
                         cudaFuncAttributeMaxDynamicSharedMemorySize, smem_bytes);

    dim3 grid(LSEQ / BQ, NBATCH);   // 32 x 16 = 512 CTAs
    attn_fwd_kernel<<<grid, 256, smem_bytes>>>(x1, x2, out);
}